// round 15
// baseline (speedup 1.0000x reference)
#include <cuda_runtime.h>
#include <cuda_bf16.h>
#include <math.h>

#define NN 64
#define CC 64
#define TT_ 128
#define VV 25

// ---------------- device scratch ----------------
__device__ float g_x1[NN*8*TT_*VV];
__device__ float g_xbarp[NN*8*1600];
__device__ __nv_bfloat162 g_D2[NN*9632];
__device__ float g_ysm[NN*8*TT_*6];
__device__ float g_ybarS[NN*6];
__device__ __nv_bfloat16 g_y1[NN*CC*TT_*VV];
__device__ float g_y1sum_nv[NN*VV];
__device__ float g_y1sum_nc[NN*CC];
__device__ float g_A12l[NN*150];
__device__ float g_gate[NN*CC];
__device__ float g_SY[CC], g_SYY[CC];
__device__ __nv_bfloat16 g_Wcp[64*256];
__device__ __nv_bfloat162 g_bc2[192];
__device__ float g_WpMean[64], g_WsMean[64];
__device__ float g_bpMean[1], g_bsMean[1];
__device__ float g_nlp[864];
__device__ float g_nlA[15000];

__device__ const int c_joints[6] = {3, 20, 7, 11, 14, 18};

__device__ __forceinline__ __nv_bfloat162 u2b(unsigned u) {
    union { unsigned u; __nv_bfloat162 b; } cv; cv.u = u; return cv.b;
}
__device__ __forceinline__ unsigned b2u(__nv_bfloat162 b) {
    union { __nv_bfloat162 b; unsigned u; } cv; cv.b = b; return cv.u;
}

// ---------------- K1f: x1 conv + xbar partials + weight folding ----------------
#define K1_SMEM_BYTES (51200 + 2048 + 32)
__global__ void __launch_bounds__(512) k1f(const float* __restrict__ x,
                                           const float* __restrict__ Wp,
                                           const float* __restrict__ bp,
                                           const float* __restrict__ W2,
                                           const float* __restrict__ Ws,
                                           const float* __restrict__ b2,
                                           const float* __restrict__ bs,
                                           const float* __restrict__ Dpap,
                                           const float* __restrict__ pa,
                                           const float* __restrict__ DecA,
                                           const float* __restrict__ A1buf) {
    int bx = blockIdx.x, tid = threadIdx.x;
    if (bx >= 512) {
        int b = bx - 512;
        if (b < 4) {
            for (int q = tid; q < 3072; q += 512) {
                int idx = b*3072 + q;
                int cj = idx / 192, r = idx % 192;
                float s = 0.f;
                #pragma unroll 8
                for (int cm = 0; cm < 64; cm++) s += W2[r*64 + cm] * Ws[cm*64 + cj];
                g_Wcp[cj*256 + (r/12)*16 + (r%12)] = __float2bfloat16(s);
            }
        } else if (b == 4) {
            for (int r = tid; r < 192; r += 512) {
                float s = 0.f;
                for (int cm = 0; cm < 64; cm++) s += W2[r*64 + cm] * bs[cm];
                g_bc2[r] = __bfloat162bfloat162(__float2bfloat16(s + b2[r]));
            }
            for (int ci = tid; ci < 64; ci += 512) {
                float s = 0.f;
                for (int o = 0; o < 8; o++) s += Wp[o*64 + ci];
                g_WpMean[ci] = s * (1.f/8.f);
                float s2 = 0.f;
                for (int c = 0; c < 64; c++) s2 += Ws[c*64 + ci];
                g_WsMean[ci] = s2 * (1.f/64.f);
            }
            if (tid == 0) {
                float s = 0.f; for (int o = 0; o < 8; o++) s += bp[o];
                g_bpMean[0] = s * (1.f/8.f);
                float s2 = 0.f; for (int c = 0; c < 64; c++) s2 += bs[c];
                g_bsMean[0] = s2 * (1.f/64.f);
            }
        } else if (b == 5) {
            for (int i = tid; i < 864; i += 512) g_nlp[i] = Dpap[i] + pa[i];
            for (int i = tid; i < NN*CC; i += 512) g_y1sum_nc[i] = 0.f;
            for (int i = tid; i < NN*VV; i += 512) g_y1sum_nv[i] = 0.f;
            if (tid < CC) { g_SY[tid] = 0.f; g_SYY[tid] = 0.f; }
        } else {
            int lo = (b - 6) * 7500;
            for (int i = tid; i < 7500; i += 512) g_nlA[lo + i] = A1buf[lo + i] + DecA[lo + i];
        }
        return;
    }
    extern __shared__ char sm1[];
    __nv_bfloat16* xt = reinterpret_cast<__nv_bfloat16*>(sm1);
    float* Wps = reinterpret_cast<float*>(sm1 + 51200);
    float* bps = Wps + 512;
    int n = bx >> 3, yb = bx & 7, t0 = yb * 16;
    const float4* x4 = reinterpret_cast<const float4*>(x);
    __nv_bfloat162* xt2 = reinterpret_cast<__nv_bfloat162*>(xt);
    int xbase4 = n*51200 + yb*100;
    for (int i = tid; i < 6400; i += 512) {
        int ci = i / 100, q = i % 100;
        float4 v = x4[xbase4 + ci*800 + q];
        xt2[ci*200 + q*2]     = __floats2bfloat162_rn(v.x, v.y);
        xt2[ci*200 + q*2 + 1] = __floats2bfloat162_rn(v.z, v.w);
    }
    if (tid < 512) Wps[tid] = Wp[tid];
    if (tid < 8) bps[tid] = bp[tid];
    __syncthreads();
    if (tid < 400) {
        int p = tid;
        float acc[8];
        #pragma unroll
        for (int o = 0; o < 8; o++) acc[o] = bps[o];
        #pragma unroll 8
        for (int ci = 0; ci < 64; ci++) {
            float xv = __bfloat162float(xt[ci*400 + p]);
            #pragma unroll
            for (int o = 0; o < 8; o++) acc[o] += Wps[o*64 + ci] * xv;
        }
        int base = (n*8*128 + t0)*25 + p;
        #pragma unroll
        for (int o = 0; o < 8; o++) g_x1[base + o*3200] = acc[o];
    } else {
        for (int i = tid - 400; i < 1600; i += 112) {
            int ci = i / 25, v = i % 25;
            float s = 0.f;
            #pragma unroll
            for (int tt = 0; tt < 16; tt++)
                s += __bfloat162float(xt[ci*400 + tt*25 + v]);
            g_xbarp[(n*8 + yb)*1600 + i] = s;
        }
    }
}

// ---------------- K2: stats + softmaxes + GCN + small-branch y + D2 pack ----------------
__global__ void __launch_bounds__(512) k2(const float* wt1p, const float* wt2p,
                   const float* wtw1p, const float* wtw2p,
                   const float* wtw11p, const float* wtw21p,
                   const float* __restrict__ W1, const float* __restrict__ b1) {
    __shared__ float xbs[1600];
    __shared__ float mb[25], xm2s[25], a1s[6], a2s[25], A12s[150], xms[6], atts[36];
    __shared__ float at2s[625];
    __shared__ float gcns[6144];
    __shared__ float W1s[192], b1s[24], Efb[864], yred[6];
    int n = blockIdx.x, tid = threadIdx.x;
    for (int i = tid; i < 1600; i += 512) {
        float s = 0.f;
        #pragma unroll
        for (int yb = 0; yb < 8; yb++) s += g_xbarp[(n*8 + yb)*1600 + i];
        xbs[i] = s;
    }
    if (tid < 192) W1s[tid] = W1[tid];
    if (tid < 24) b1s[tid] = b1[tid];
    if (tid < 6) yred[tid] = 0.f;
    __syncthreads();
    if (tid < 25) {
        float d1 = 0.f, d2 = 0.f;
        for (int ci = 0; ci < 64; ci++) {
            float xv = xbs[ci*25 + tid] * (1.f/128.f);
            d1 += xv * g_WpMean[ci];
            d2 += xv * g_WsMean[ci];
        }
        mb[tid] = d1 + g_bpMean[0];
        xm2s[tid] = d2 + g_bsMean[0];
    }
    __syncthreads();
    float wt1 = *wt1p, wt2 = *wt2p;
    if (tid < 25) a2s[tid] = fmaxf(wt2 * mb[tid], 0.f);
    if (tid < 6)  a1s[tid] = fmaxf(wt1 * mb[c_joints[tid]], 0.f);
    __syncthreads();
    if (tid < 25) {
        float e[6], mx = -1e30f;
        #pragma unroll
        for (int j = 0; j < 6; j++) { e[j] = a1s[j] * a2s[tid]; mx = fmaxf(mx, e[j]); }
        float sm = 0.f;
        #pragma unroll
        for (int j = 0; j < 6; j++) { e[j] = expf(e[j] - mx); sm += e[j]; }
        float inv = 1.f / sm;
        #pragma unroll
        for (int j = 0; j < 6; j++) A12s[j*25 + tid] = e[j] * inv;
    }
    __syncthreads();
    if (tid < 6) {
        float s = 0.f;
        for (int v = 0; v < 25; v++) s += mb[v] * A12s[tid*25 + v];
        xms[tid] = s;
    }
    __syncthreads();
    float wtw1 = *wtw1p, wtw2 = *wtw2p;
    if (tid < 6) {
        float r2w = fmaxf(wtw2 * xms[tid], 0.f);
        float e[6], mx = -1e30f;
        #pragma unroll
        for (int j = 0; j < 6; j++) { e[j] = fmaxf(wtw1 * xms[j], 0.f) * r2w; mx = fmaxf(mx, e[j]); }
        float sm = 0.f;
        #pragma unroll
        for (int j = 0; j < 6; j++) { e[j] = expf(e[j] - mx); sm += e[j]; }
        float inv = 1.f / sm;
        #pragma unroll
        for (int j = 0; j < 6; j++) atts[j*6 + tid] = e[j] * inv;
    }
    float wtw11 = *wtw11p, wtw21 = *wtw21p;
    if (tid < 25) {
        float r2w = fmaxf(wtw21 * xm2s[tid], 0.f);
        float e[25], mx = -1e30f;
        #pragma unroll
        for (int v = 0; v < 25; v++) { e[v] = fmaxf(wtw11 * xm2s[v], 0.f) * r2w; mx = fmaxf(mx, e[v]); }
        float sm = 0.f;
        #pragma unroll
        for (int v = 0; v < 25; v++) { e[v] = expf(e[v] - mx); sm += e[v]; }
        float inv = 1.f / sm;
        #pragma unroll
        for (int v = 0; v < 25; v++) at2s[v*25 + tid] = e[v] * inv;
    }
    __syncthreads();
    for (int ot = tid; ot < 1024; ot += 512) {
        int o = ot >> 7, t = ot & 127;
        const float* xr = g_x1 + ((n*8 + o)*128 + t)*25;
        float xv[25];
        #pragma unroll
        for (int v = 0; v < 25; v++) xv[v] = xr[v];
        #pragma unroll
        for (int j = 0; j < 6; j++) {
            float s = 0.f;
            #pragma unroll
            for (int v = 0; v < 25; v++) s += xv[v] * A12s[j*25 + v];
            gcns[(o*128 + t)*6 + j] = s;
        }
    }
    for (int i = tid; i < 864; i += 512) Efb[i] = 0.5f * atts[i % 36] + g_nlp[i];
    __syncthreads();
    {
        float lsum[6] = {0.f, 0.f, 0.f, 0.f, 0.f, 0.f};
        for (int gt = tid; gt < 1024; gt += 512) {
            int g = gt >> 7, t = gt & 127;
            float mloc[3][6];
            #pragma unroll
            for (int k = 0; k < 3; k++) {
                const float* wrow = &W1s[(k*8 + g)*8];
                float bb = b1s[k*8 + g];
                #pragma unroll
                for (int j = 0; j < 6; j++) {
                    float s = bb;
                    #pragma unroll
                    for (int o = 0; o < 8; o++) s += gcns[(o*128 + t)*6 + j] * wrow[o];
                    mloc[k][j] = s;
                }
            }
            #pragma unroll
            for (int w = 0; w < 6; w++) {
                float s = 0.f;
                #pragma unroll
                for (int k = 0; k < 3; k++)
                    #pragma unroll
                    for (int j = 0; j < 6; j++)
                        s += mloc[k][j] * Efb[((k*8 + g)*6 + j)*6 + w];
                g_ysm[(n*8 + g)*768 + t*6 + w] = s;
                lsum[w] += s;
            }
        }
        #pragma unroll
        for (int w = 0; w < 6; w++) {
            float s = lsum[w];
            #pragma unroll
            for (int off = 16; off > 0; off >>= 1)
                s += __shfl_xor_sync(0xffffffffu, s, off);
            if ((tid & 31) == 0) atomicAdd(&yred[w], s);
        }
    }
    for (int i = tid; i < 9632; i += 512) {
        int g = i / 1204, r = i % 1204;
        int kv = r >> 4, w2 = r & 15;
        float v0 = 0.f, v1 = 0.f;
        if (kv < 75) {
            int k = kv / 25, v = kv % 25;
            int w0 = w2*2, w1 = w0 + 1;
            if (w0 < 25) v0 = g_nlA[((k*8 + g)*25 + v)*25 + w0] + 0.5f * at2s[v*25 + w0];
            if (w1 < 25) v1 = g_nlA[((k*8 + g)*25 + v)*25 + w1] + 0.5f * at2s[v*25 + w1];
        }
        g_D2[n*9632 + i] = __floats2bfloat162_rn(v0, v1);
    }
    __syncthreads();
    if (tid < 6) g_ybarS[n*6 + tid] = yred[tid] * (1.f/1024.f);
}

// ---------------- K5: y1 kernel (R11 winner, unchanged) ----------------
#define K5_D_OFF 0
#define K5_M_OFF 38528
#define K5_X_OFF 77696
#define K5_R_OFF 91008
#define K5_B_OFF 91520
#define K5_SMEM_BYTES 92288
__global__ void __launch_bounds__(512, 2) k5(const float* __restrict__ x) {
    extern __shared__ char smem[];
    __nv_bfloat162* Dsm = reinterpret_cast<__nv_bfloat162*>(smem + K5_D_OFF);
    unsigned* m2u = reinterpret_cast<unsigned*>(smem + K5_M_OFF);
    __nv_bfloat16*  xsm = reinterpret_cast<__nv_bfloat16*>(smem + K5_X_OFF);
    __nv_bfloat16*  ybuf = reinterpret_cast<__nv_bfloat16*>(smem + K5_X_OFF);
    float* red = reinterpret_cast<float*>(smem + K5_R_OFF);
    __nv_bfloat162* bcs = reinterpret_cast<__nv_bfloat162*>(smem + K5_B_OFF);
    int n = blockIdx.x, t0 = blockIdx.y * 4, tid = threadIdx.x;
    if (tid < 128) red[tid] = 0.f;
    if (tid < 192) bcs[tid] = g_bc2[tid];
    {
        const uint4* ds = reinterpret_cast<const uint4*>(g_D2 + n*9632);
        uint4* dd = reinterpret_cast<uint4*>(Dsm);
        for (int i = tid; i < 2408; i += 512) dd[i] = ds[i];
        const float4* x4 = reinterpret_cast<const float4*>(x);
        int xb = n*51200 + (t0*25)/4;
        for (int i = tid; i < 1600; i += 512) {
            int ci = i / 25, q = i % 25;
            float4 v = x4[xb + ci*800 + q];
            float vals[4] = {v.x, v.y, v.z, v.w};
            #pragma unroll
            for (int e = 0; e < 4; e++) {
                int pl = q*4 + e;
                int tt = (pl*41) >> 10;
                int vv = pl - tt*25;
                xsm[ci*100 + vv*4 + tt] = __float2bfloat16(vals[e]);
            }
        }
    }
    __syncthreads();
    if (tid < 400) {
        int pp = tid % 25, rq = tid / 25;
        __nv_bfloat162 acc[6][4];
        #pragma unroll
        for (int h = 0; h < 6; h++)
            #pragma unroll
            for (int j = 0; j < 4; j++) acc[h][j] = u2b(0u);
        #pragma unroll 4
        for (int ci = 0; ci < 64; ci++) {
            const uint4* wb = reinterpret_cast<const uint4*>(g_Wcp + ci*256 + rq*16);
            uint4 w0 = __ldg(wb), w1 = __ldg(wb + 1);
            __nv_bfloat162 wp[6] = {u2b(w0.x), u2b(w0.y), u2b(w0.z),
                                    u2b(w0.w), u2b(w1.x), u2b(w1.y)};
            uint2 xq = *reinterpret_cast<const uint2*>(xsm + ci*100 + pp*4);
            __nv_bfloat162 xa = u2b(xq.x), xb2 = u2b(xq.y);
            __nv_bfloat162 xs[4];
            xs[0] = __bfloat162bfloat162(__low2bfloat16(xa));
            xs[1] = __bfloat162bfloat162(__high2bfloat16(xa));
            xs[2] = __bfloat162bfloat162(__low2bfloat16(xb2));
            xs[3] = __bfloat162bfloat162(__high2bfloat16(xb2));
            #pragma unroll
            for (int h = 0; h < 6; h++)
                #pragma unroll
                for (int j = 0; j < 4; j++)
                    acc[h][j] = __hfma2(wp[h], xs[j], acc[h][j]);
        }
        int r0 = rq * 12;
        #pragma unroll
        for (int h = 0; h < 6; h++) {
            __nv_bfloat162 lo01 = __lows2bfloat162(acc[h][0], acc[h][1]);
            __nv_bfloat162 lo23 = __lows2bfloat162(acc[h][2], acc[h][3]);
            __nv_bfloat162 hi01 = __highs2bfloat162(acc[h][0], acc[h][1]);
            __nv_bfloat162 hi23 = __highs2bfloat162(acc[h][2], acc[h][3]);
            __nv_bfloat162 be = bcs[r0 + 2*h], bo = bcs[r0 + 2*h + 1];
            int re = r0 + 2*h, ro = re + 1;
            m2u[re*51 + pp*2]     = b2u(__hadd2(lo01, be));
            m2u[re*51 + pp*2 + 1] = b2u(__hadd2(lo23, be));
            m2u[ro*51 + pp*2]     = b2u(__hadd2(hi01, bo));
            m2u[ro*51 + pp*2 + 1] = b2u(__hadd2(hi23, bo));
        }
    }
    __syncthreads();
    {
        int c = tid & 63, wq = (tid >> 6) & 3, th = tid >> 8;
        int g = c & 7;
        __nv_bfloat162 acc[2][4];
        #pragma unroll
        for (int tt = 0; tt < 2; tt++)
            #pragma unroll
            for (int j = 0; j < 4; j++) acc[tt][j] = u2b(0u);
        const uint4* Dv = reinterpret_cast<const uint4*>(Dsm);
        #pragma unroll
        for (int k = 0; k < 3; k++) {
            const unsigned* mrow = m2u + (k*64 + c)*51 + th;
            const uint4* db = Dv + g*301 + k*100 + wq;
            #pragma unroll 5
            for (int v = 0; v < 25; v++) {
                uint4 dq = db[v*4];
                __nv_bfloat162 d0 = u2b(dq.x), d1 = u2b(dq.y),
                               d2 = u2b(dq.z), d3 = u2b(dq.w);
                __nv_bfloat162 mp = u2b(mrow[v*2]);
                __nv_bfloat162 m0 = __bfloat162bfloat162(__low2bfloat16(mp));
                __nv_bfloat162 m1 = __bfloat162bfloat162(__high2bfloat16(mp));
                acc[0][0] = __hfma2(m0, d0, acc[0][0]);
                acc[0][1] = __hfma2(m0, d1, acc[0][1]);
                acc[0][2] = __hfma2(m0, d2, acc[0][2]);
                acc[0][3] = __hfma2(m0, d3, acc[0][3]);
                acc[1][0] = __hfma2(m1, d0, acc[1][0]);
                acc[1][1] = __hfma2(m1, d1, acc[1][1]);
                acc[1][2] = __hfma2(m1, d2, acc[1][2]);
                acc[1][3] = __hfma2(m1, d3, acc[1][3]);
            }
        }
        float csum = 0.f;
        #pragma unroll
        for (int j = 0; j < 4; j++) {
            int w0 = wq*8 + 2*j;
            if (w0 > 24) continue;
            float s0 = 0.f, s1 = 0.f;
            #pragma unroll
            for (int tt = 0; tt < 2; tt++) {
                int trow = th*2 + tt;
                *reinterpret_cast<__nv_bfloat162*>(ybuf + (c*4 + trow)*26 + w0) = acc[tt][j];
                float2 f = __bfloat1622float2(acc[tt][j]);
                s0 += f.x; s1 += f.y;
            }
            csum += s0;
            if (w0 + 1 < 25) csum += s1;
            #pragma unroll
            for (int off = 16; off > 0; off >>= 1) {
                s0 += __shfl_xor_sync(0xffffffffu, s0, off);
                s1 += __shfl_xor_sync(0xffffffffu, s1, off);
            }
            if ((tid & 31) == 0) {
                atomicAdd(&red[w0], s0);
                if (w0 + 1 < 25) atomicAdd(&red[w0 + 1], s1);
            }
        }
        atomicAdd(&red[32 + c], csum);
    }
    __syncthreads();
    for (int i = tid; i < 1600; i += 512) {
        int c = i / 25, q = i % 25;
        uint2 u;
        __nv_bfloat16* tmp = reinterpret_cast<__nv_bfloat16*>(&u);
        #pragma unroll
        for (int e = 0; e < 4; e++) {
            int lin = q*4 + e;
            int tt = (lin*41) >> 10;
            int w = lin - tt*25;
            tmp[e] = ybuf[(c*4 + tt)*26 + w];
        }
        *reinterpret_cast<uint2*>(g_y1 + n*204800 + c*3200 + t0*25 + q*4) = u;
    }
    if (tid < 25) atomicAdd(&g_y1sum_nv[n*25 + tid], red[tid]);
    if (tid >= 32 && tid < 96) atomicAdd(&g_y1sum_nc[n*64 + tid - 32], red[tid]);
}

// ---------------- K6s: per-n stats -> g_A12l, g_gate ----------------
__global__ void __launch_bounds__(384) k6s(const float* ws1p, const float* ws2p,
                    const float* __restrict__ We, const float* __restrict__ be,
                    const float* __restrict__ kca) {
    __shared__ float A12ls[150], a1ls[6], ytsum[48], Asum[6], Ssum[8], qs[64];
    int n = blockIdx.x, tid = threadIdx.x;
    if (tid < 48) ytsum[tid] = 0.f;
    if (tid < 6) a1ls[tid] = fmaxf((*ws1p) * g_ybarS[n*6 + tid], 0.f);
    __syncthreads();
    // ytsum: 48 entries x 8 partials of 16 t's
    {
        int entry = tid >> 3, part = tid & 7;
        int o = entry / 6, j = entry % 6;
        const float* yp = g_ysm + (n*8 + o)*768 + part*96 + j;
        float s = 0.f;
        #pragma unroll
        for (int t = 0; t < 16; t++) s += yp[t*6];
        #pragma unroll
        for (int off = 4; off > 0; off >>= 1)
            s += __shfl_down_sync(0xffffffffu, s, off);
        if (part == 0) ytsum[entry] = s;
    }
    __syncthreads();
    if (tid < 25) {
        float a2 = fmaxf((*ws2p) * g_y1sum_nv[n*25 + tid] * (1.f/8192.f), 0.f);
        float e[6], mx = -1e30f;
        #pragma unroll
        for (int j = 0; j < 6; j++) { e[j] = a1ls[j] * a2; mx = fmaxf(mx, e[j]); }
        float s = 0.f;
        #pragma unroll
        for (int j = 0; j < 6; j++) { e[j] = expf(e[j] - mx); s += e[j]; }
        float inv = 1.f / s;
        #pragma unroll
        for (int j = 0; j < 6; j++) {
            float v = e[j] * inv;
            A12ls[j*25 + tid] = v;
            g_A12l[n*150 + j*25 + tid] = v;
        }
    }
    __syncthreads();
    if (tid < 6) {
        float s = 0.f;
        for (int v = 0; v < 25; v++) s += A12ls[tid*25 + v];
        Asum[tid] = s;
    }
    __syncthreads();
    if (tid < 8) {
        float s = 0.f;
        #pragma unroll
        for (int j = 0; j < 6; j++) s += ytsum[tid*6 + j] * Asum[j];
        Ssum[tid] = s;
    }
    __syncthreads();
    if (tid < 64) {
        float yls = 3200.f * be[tid];
        #pragma unroll
        for (int o = 0; o < 8; o++) yls += We[tid*8 + o] * Ssum[o];
        qs[tid] = (g_y1sum_nc[n*64 + tid] + 0.5f * yls) * (1.f/3200.f);
    }
    __syncthreads();
    if (tid < 64) {
        float qm = (tid > 0) ? qs[tid-1] : 0.f;
        float q0 = qs[tid];
        float qp1 = (tid < 63) ? qs[tid+1] : 0.f;
        float qc = kca[0]*qm + kca[1]*q0 + kca[2]*qp1;
        g_gate[n*64 + tid] = 1.f + 1.f/(1.f + expf(-qc));
    }
}

// ---------------- K76: Y pass + BN stats (stats precomputed) ----------------
__global__ void k76(const float* __restrict__ We, const float* __restrict__ be) {
    __shared__ float A12ls[150], Wes[512], bes[64], gates[64], ytile[768], zs[3200];
    int n = blockIdx.x, t0 = blockIdx.y * 16, tid = threadIdx.x;
    for (int i = tid; i < 512; i += 256) Wes[i] = We[i];
    if (tid < 64) { bes[tid] = be[tid]; gates[tid] = g_gate[n*64 + tid]; }
    if (tid >= 64 && tid < 214) A12ls[tid - 64] = g_A12l[n*150 + tid - 64];
    for (int i = tid; i < 768; i += 256) {
        int o = i / 96, r = i % 96, t = r / 6, j = r % 6;
        ytile[i] = g_ysm[(n*8 + o)*768 + (t0 + t)*6 + j];
    }
    __syncthreads();
    for (int i = tid; i < 3200; i += 256) {
        int o = i / 400, r = i % 400, t = r / 25, v = r % 25;
        float s = 0.f;
        #pragma unroll
        for (int j = 0; j < 6; j++) s += ytile[o*96 + t*6 + j] * A12ls[j*25 + v];
        zs[i] = s;
    }
    __syncthreads();
    int warp = tid >> 5, lane = tid & 31;
    for (int cc = warp; cc < 64; cc += 8) {
        float wrow[8];
        #pragma unroll
        for (int o = 0; o < 8; o++) wrow[o] = Wes[cc*8 + o];
        float bc = bes[cc], gt = gates[cc];
        float lsy = 0.f, lsyy = 0.f;
        int base = ((n*64 + cc)*128 + t0)*25;
        __nv_bfloat16* yb16 = g_y1 + base;
        for (int e = lane; e < 400; e += 32) {
            float yl = bc;
            #pragma unroll
            for (int o = 0; o < 8; o++) yl += wrow[o] * zs[o*400 + e];
            float Y = (0.5f*yl + __bfloat162float(yb16[e])) * gt;
            yb16[e] = __float2bfloat16(Y);
            lsy += Y;
            lsyy += Y * Y;
        }
        #pragma unroll
        for (int off = 16; off > 0; off >>= 1) {
            lsy  += __shfl_down_sync(0xffffffffu, lsy, off);
            lsyy += __shfl_down_sync(0xffffffffu, lsyy, off);
        }
        if (lane == 0) {
            atomicAdd(&g_SY[cc], lsy);
            atomicAdd(&g_SYY[cc], lsyy);
        }
    }
}

// ---------------- K9: out = relu(BN(Yg) + x), BN inline ----------------
__global__ void __launch_bounds__(512) k9(const float* __restrict__ x,
                   const float* __restrict__ bn_g, const float* __restrict__ bn_b,
                   float* __restrict__ out) {
    int i = blockIdx.x * 512 + threadIdx.x;
    if (i >= 3276800) return;
    int c = (i / 800) & 63;
    const float icnt = 1.f/204800.f;
    float mu = g_SY[c] * icnt;
    float var = g_SYY[c] * icnt - mu*mu;
    float sc = bn_g[c] * rsqrtf(var + 1e-5f);
    float sh = bn_b[c] - mu*sc;
    const __nv_bfloat162* y2 = reinterpret_cast<const __nv_bfloat162*>(g_y1);
    __nv_bfloat162 ya = y2[i*2], yb = y2[i*2 + 1];
    float4 xv = reinterpret_cast<const float4*>(x)[i];
    float4 o;
    o.x = fmaxf(__bfloat162float(ya.x)*sc + sh + xv.x, 0.f);
    o.y = fmaxf(__bfloat162float(ya.y)*sc + sh + xv.y, 0.f);
    o.z = fmaxf(__bfloat162float(yb.x)*sc + sh + xv.z, 0.f);
    o.w = fmaxf(__bfloat162float(yb.y)*sc + sh + xv.w, 0.f);
    reinterpret_cast<float4*>(out)[i] = o;
}

// ---------------- launch ----------------
extern "C" void kernel_launch(void* const* d_in, const int* in_sizes, int n_in,
                              void* d_out, int out_size) {
    const float* x     = (const float*)d_in[0];
    const float* Dpap  = (const float*)d_in[1];
    const float* pa    = (const float*)d_in[2];
    const float* DecA  = (const float*)d_in[3];
    const float* A1buf = (const float*)d_in[4];
    const float* Wp    = (const float*)d_in[5];
    const float* bp    = (const float*)d_in[6];
    const float* Ws    = (const float*)d_in[7];
    const float* bs    = (const float*)d_in[8];
    const float* W1    = (const float*)d_in[9];
    const float* b1    = (const float*)d_in[10];
    const float* W2    = (const float*)d_in[11];
    const float* b2    = (const float*)d_in[12];
    const float* We    = (const float*)d_in[13];
    const float* be    = (const float*)d_in[14];
    const float* wt1   = (const float*)d_in[15];
    const float* wt2   = (const float*)d_in[16];
    const float* wtw1  = (const float*)d_in[17];
    const float* wtw2  = (const float*)d_in[18];
    const float* wtw11 = (const float*)d_in[19];
    const float* wtw21 = (const float*)d_in[20];
    const float* ws1   = (const float*)d_in[21];
    const float* ws2   = (const float*)d_in[22];
    const float* kca   = (const float*)d_in[23];
    const float* bn_g  = (const float*)d_in[24];
    const float* bn_b  = (const float*)d_in[25];
    float* out = (float*)d_out;

    cudaFuncSetAttribute(k5, cudaFuncAttributeMaxDynamicSharedMemorySize,
                         K5_SMEM_BYTES);
    cudaFuncSetAttribute(k1f, cudaFuncAttributeMaxDynamicSharedMemorySize,
                         K1_SMEM_BYTES);

    k1f<<<520, 512, K1_SMEM_BYTES>>>(x, Wp, bp, W2, Ws, b2, bs,
                                     Dpap, pa, DecA, A1buf);
    k2<<<64, 512>>>(wt1, wt2, wtw1, wtw2, wtw11, wtw21, W1, b1);
    k5<<<dim3(64, 32), 512, K5_SMEM_BYTES>>>(x);
    k6s<<<64, 384>>>(ws1, ws2, We, be, kca);
    k76<<<dim3(64, 8), 256>>>(We, be);
    k9<<<6400, 512>>>(x, bn_g, bn_b, out);
}

// round 16
// speedup vs baseline: 1.5631x; 1.5631x over previous
#include <cuda_runtime.h>
#include <cuda_bf16.h>
#include <math.h>

#define NN 64
#define CC 64
#define TT_ 128
#define VV 25

// ---------------- device scratch ----------------
__device__ float g_x1[NN*8*TT_*VV];
__device__ float g_xbarp[NN*8*1600];
__device__ __nv_bfloat162 g_D2[NN*9632];
__device__ float g_ysm[NN*8*TT_*6];
__device__ float g_ybarS[NN*6];
__device__ __nv_bfloat16 g_y1[NN*CC*TT_*VV];
__device__ float g_y1sum_nv[NN*VV];
__device__ float g_y1sum_nc[NN*CC];
__device__ float g_SY[CC], g_SYY[CC];
__device__ __nv_bfloat16 g_Wcp[64*256];
__device__ __nv_bfloat162 g_bc2[192];
__device__ float g_WpMean[64], g_WsMean[64];
__device__ float g_bpMean[1], g_bsMean[1];
__device__ float g_nlp[864];
__device__ float g_nlA[15000];

__device__ const int c_joints[6] = {3, 20, 7, 11, 14, 18};

__device__ __forceinline__ __nv_bfloat162 u2b(unsigned u) {
    union { unsigned u; __nv_bfloat162 b; } cv; cv.u = u; return cv.b;
}
__device__ __forceinline__ unsigned b2u(__nv_bfloat162 b) {
    union { __nv_bfloat162 b; unsigned u; } cv; cv.b = b; return cv.u;
}

// ---------------- K1f: x1 conv + xbar partials + weight folding ----------------
#define K1_SMEM_BYTES (51200 + 2048 + 32)
__global__ void __launch_bounds__(512) k1f(const float* __restrict__ x,
                                           const float* __restrict__ Wp,
                                           const float* __restrict__ bp,
                                           const float* __restrict__ W2,
                                           const float* __restrict__ Ws,
                                           const float* __restrict__ b2,
                                           const float* __restrict__ bs,
                                           const float* __restrict__ Dpap,
                                           const float* __restrict__ pa,
                                           const float* __restrict__ DecA,
                                           const float* __restrict__ A1buf) {
    int bx = blockIdx.x, tid = threadIdx.x;
    if (bx >= 512) {
        int b = bx - 512;
        if (b < 4) {
            for (int q = tid; q < 3072; q += 512) {
                int idx = b*3072 + q;
                int cj = idx / 192, r = idx % 192;
                float s = 0.f;
                #pragma unroll 8
                for (int cm = 0; cm < 64; cm++) s += W2[r*64 + cm] * Ws[cm*64 + cj];
                g_Wcp[cj*256 + (r/12)*16 + (r%12)] = __float2bfloat16(s);
            }
        } else if (b == 4) {
            for (int r = tid; r < 192; r += 512) {
                float s = 0.f;
                for (int cm = 0; cm < 64; cm++) s += W2[r*64 + cm] * bs[cm];
                g_bc2[r] = __bfloat162bfloat162(__float2bfloat16(s + b2[r]));
            }
            for (int ci = tid; ci < 64; ci += 512) {
                float s = 0.f;
                for (int o = 0; o < 8; o++) s += Wp[o*64 + ci];
                g_WpMean[ci] = s * (1.f/8.f);
                float s2 = 0.f;
                for (int c = 0; c < 64; c++) s2 += Ws[c*64 + ci];
                g_WsMean[ci] = s2 * (1.f/64.f);
            }
            if (tid == 0) {
                float s = 0.f; for (int o = 0; o < 8; o++) s += bp[o];
                g_bpMean[0] = s * (1.f/8.f);
                float s2 = 0.f; for (int c = 0; c < 64; c++) s2 += bs[c];
                g_bsMean[0] = s2 * (1.f/64.f);
            }
        } else if (b == 5) {
            for (int i = tid; i < 864; i += 512) g_nlp[i] = Dpap[i] + pa[i];
            for (int i = tid; i < NN*CC; i += 512) g_y1sum_nc[i] = 0.f;
            for (int i = tid; i < NN*VV; i += 512) g_y1sum_nv[i] = 0.f;
            if (tid < CC) { g_SY[tid] = 0.f; g_SYY[tid] = 0.f; }
        } else {
            int lo = (b - 6) * 7500;
            for (int i = tid; i < 7500; i += 512) g_nlA[lo + i] = A1buf[lo + i] + DecA[lo + i];
        }
        return;
    }
    extern __shared__ char sm1[];
    __nv_bfloat16* xt = reinterpret_cast<__nv_bfloat16*>(sm1);
    float* Wps = reinterpret_cast<float*>(sm1 + 51200);
    float* bps = Wps + 512;
    int n = bx >> 3, yb = bx & 7, t0 = yb * 16;
    const float4* x4 = reinterpret_cast<const float4*>(x);
    __nv_bfloat162* xt2 = reinterpret_cast<__nv_bfloat162*>(xt);
    int xbase4 = n*51200 + yb*100;
    for (int i = tid; i < 6400; i += 512) {
        int ci = i / 100, q = i % 100;
        float4 v = x4[xbase4 + ci*800 + q];
        xt2[ci*200 + q*2]     = __floats2bfloat162_rn(v.x, v.y);
        xt2[ci*200 + q*2 + 1] = __floats2bfloat162_rn(v.z, v.w);
    }
    if (tid < 512) Wps[tid] = Wp[tid];
    if (tid < 8) bps[tid] = bp[tid];
    __syncthreads();
    if (tid < 400) {
        int p = tid;
        float acc[8];
        #pragma unroll
        for (int o = 0; o < 8; o++) acc[o] = bps[o];
        #pragma unroll 8
        for (int ci = 0; ci < 64; ci++) {
            float xv = __bfloat162float(xt[ci*400 + p]);
            #pragma unroll
            for (int o = 0; o < 8; o++) acc[o] += Wps[o*64 + ci] * xv;
        }
        int base = (n*8*128 + t0)*25 + p;
        #pragma unroll
        for (int o = 0; o < 8; o++) g_x1[base + o*3200] = acc[o];
    } else {
        for (int i = tid - 400; i < 1600; i += 112) {
            int ci = i / 25, v = i % 25;
            float s = 0.f;
            #pragma unroll
            for (int tt = 0; tt < 16; tt++)
                s += __bfloat162float(xt[ci*400 + tt*25 + v]);
            g_xbarp[(n*8 + yb)*1600 + i] = s;
        }
    }
}

// ---------------- K2: stats + softmaxes + GCN + small-branch y + D2 pack ----------------
__global__ void __launch_bounds__(512) k2(const float* wt1p, const float* wt2p,
                   const float* wtw1p, const float* wtw2p,
                   const float* wtw11p, const float* wtw21p,
                   const float* __restrict__ W1, const float* __restrict__ b1) {
    __shared__ float xbs[1600];
    __shared__ float mb[25], xm2s[25], a1s[6], a2s[25], A12s[150], xms[6], atts[36];
    __shared__ float at2s[625];
    __shared__ float gcns[6144];
    __shared__ float W1s[192], b1s[24], Efb[864], yred[6];
    int n = blockIdx.x, tid = threadIdx.x;
    for (int i = tid; i < 1600; i += 512) {
        float s = 0.f;
        #pragma unroll
        for (int yb = 0; yb < 8; yb++) s += g_xbarp[(n*8 + yb)*1600 + i];
        xbs[i] = s;
    }
    if (tid < 192) W1s[tid] = W1[tid];
    if (tid < 24) b1s[tid] = b1[tid];
    if (tid < 6) yred[tid] = 0.f;
    __syncthreads();
    if (tid < 25) {
        float d1 = 0.f, d2 = 0.f;
        for (int ci = 0; ci < 64; ci++) {
            float xv = xbs[ci*25 + tid] * (1.f/128.f);
            d1 += xv * g_WpMean[ci];
            d2 += xv * g_WsMean[ci];
        }
        mb[tid] = d1 + g_bpMean[0];
        xm2s[tid] = d2 + g_bsMean[0];
    }
    __syncthreads();
    float wt1 = *wt1p, wt2 = *wt2p;
    if (tid < 25) a2s[tid] = fmaxf(wt2 * mb[tid], 0.f);
    if (tid < 6)  a1s[tid] = fmaxf(wt1 * mb[c_joints[tid]], 0.f);
    __syncthreads();
    if (tid < 25) {
        float e[6], mx = -1e30f;
        #pragma unroll
        for (int j = 0; j < 6; j++) { e[j] = a1s[j] * a2s[tid]; mx = fmaxf(mx, e[j]); }
        float sm = 0.f;
        #pragma unroll
        for (int j = 0; j < 6; j++) { e[j] = expf(e[j] - mx); sm += e[j]; }
        float inv = 1.f / sm;
        #pragma unroll
        for (int j = 0; j < 6; j++) A12s[j*25 + tid] = e[j] * inv;
    }
    __syncthreads();
    if (tid < 6) {
        float s = 0.f;
        for (int v = 0; v < 25; v++) s += mb[v] * A12s[tid*25 + v];
        xms[tid] = s;
    }
    __syncthreads();
    float wtw1 = *wtw1p, wtw2 = *wtw2p;
    if (tid < 6) {
        float r2w = fmaxf(wtw2 * xms[tid], 0.f);
        float e[6], mx = -1e30f;
        #pragma unroll
        for (int j = 0; j < 6; j++) { e[j] = fmaxf(wtw1 * xms[j], 0.f) * r2w; mx = fmaxf(mx, e[j]); }
        float sm = 0.f;
        #pragma unroll
        for (int j = 0; j < 6; j++) { e[j] = expf(e[j] - mx); sm += e[j]; }
        float inv = 1.f / sm;
        #pragma unroll
        for (int j = 0; j < 6; j++) atts[j*6 + tid] = e[j] * inv;
    }
    float wtw11 = *wtw11p, wtw21 = *wtw21p;
    if (tid < 25) {
        float r2w = fmaxf(wtw21 * xm2s[tid], 0.f);
        float e[25], mx = -1e30f;
        #pragma unroll
        for (int v = 0; v < 25; v++) { e[v] = fmaxf(wtw11 * xm2s[v], 0.f) * r2w; mx = fmaxf(mx, e[v]); }
        float sm = 0.f;
        #pragma unroll
        for (int v = 0; v < 25; v++) { e[v] = expf(e[v] - mx); sm += e[v]; }
        float inv = 1.f / sm;
        #pragma unroll
        for (int v = 0; v < 25; v++) at2s[v*25 + tid] = e[v] * inv;
    }
    __syncthreads();
    for (int ot = tid; ot < 1024; ot += 512) {
        int o = ot >> 7, t = ot & 127;
        const float* xr = g_x1 + ((n*8 + o)*128 + t)*25;
        float xv[25];
        #pragma unroll
        for (int v = 0; v < 25; v++) xv[v] = xr[v];
        #pragma unroll
        for (int j = 0; j < 6; j++) {
            float s = 0.f;
            #pragma unroll
            for (int v = 0; v < 25; v++) s += xv[v] * A12s[j*25 + v];
            gcns[(o*128 + t)*6 + j] = s;
        }
    }
    for (int i = tid; i < 864; i += 512) Efb[i] = 0.5f * atts[i % 36] + g_nlp[i];
    __syncthreads();
    {
        float lsum[6] = {0.f, 0.f, 0.f, 0.f, 0.f, 0.f};
        for (int gt = tid; gt < 1024; gt += 512) {
            int g = gt >> 7, t = gt & 127;
            float mloc[3][6];
            #pragma unroll
            for (int k = 0; k < 3; k++) {
                const float* wrow = &W1s[(k*8 + g)*8];
                float bb = b1s[k*8 + g];
                #pragma unroll
                for (int j = 0; j < 6; j++) {
                    float s = bb;
                    #pragma unroll
                    for (int o = 0; o < 8; o++) s += gcns[(o*128 + t)*6 + j] * wrow[o];
                    mloc[k][j] = s;
                }
            }
            #pragma unroll
            for (int w = 0; w < 6; w++) {
                float s = 0.f;
                #pragma unroll
                for (int k = 0; k < 3; k++)
                    #pragma unroll
                    for (int j = 0; j < 6; j++)
                        s += mloc[k][j] * Efb[((k*8 + g)*6 + j)*6 + w];
                g_ysm[(n*8 + g)*768 + t*6 + w] = s;
                lsum[w] += s;
            }
        }
        #pragma unroll
        for (int w = 0; w < 6; w++) {
            float s = lsum[w];
            #pragma unroll
            for (int off = 16; off > 0; off >>= 1)
                s += __shfl_xor_sync(0xffffffffu, s, off);
            if ((tid & 31) == 0) atomicAdd(&yred[w], s);
        }
    }
    for (int i = tid; i < 9632; i += 512) {
        int g = i / 1204, r = i % 1204;
        int kv = r >> 4, w2 = r & 15;
        float v0 = 0.f, v1 = 0.f;
        if (kv < 75) {
            int k = kv / 25, v = kv % 25;
            int w0 = w2*2, w1 = w0 + 1;
            if (w0 < 25) v0 = g_nlA[((k*8 + g)*25 + v)*25 + w0] + 0.5f * at2s[v*25 + w0];
            if (w1 < 25) v1 = g_nlA[((k*8 + g)*25 + v)*25 + w1] + 0.5f * at2s[v*25 + w1];
        }
        g_D2[n*9632 + i] = __floats2bfloat162_rn(v0, v1);
    }
    __syncthreads();
    if (tid < 6) g_ybarS[n*6 + tid] = yred[tid] * (1.f/1024.f);
}

// ---------------- K5: y1 kernel (R11 winner, unchanged) ----------------
#define K5_D_OFF 0
#define K5_M_OFF 38528
#define K5_X_OFF 77696
#define K5_R_OFF 91008
#define K5_B_OFF 91520
#define K5_SMEM_BYTES 92288
__global__ void __launch_bounds__(512, 2) k5(const float* __restrict__ x) {
    extern __shared__ char smem[];
    __nv_bfloat162* Dsm = reinterpret_cast<__nv_bfloat162*>(smem + K5_D_OFF);
    unsigned* m2u = reinterpret_cast<unsigned*>(smem + K5_M_OFF);
    __nv_bfloat16*  xsm = reinterpret_cast<__nv_bfloat16*>(smem + K5_X_OFF);
    __nv_bfloat16*  ybuf = reinterpret_cast<__nv_bfloat16*>(smem + K5_X_OFF);
    float* red = reinterpret_cast<float*>(smem + K5_R_OFF);
    __nv_bfloat162* bcs = reinterpret_cast<__nv_bfloat162*>(smem + K5_B_OFF);
    int n = blockIdx.x, t0 = blockIdx.y * 4, tid = threadIdx.x;
    if (tid < 128) red[tid] = 0.f;
    if (tid < 192) bcs[tid] = g_bc2[tid];
    {
        const uint4* ds = reinterpret_cast<const uint4*>(g_D2 + n*9632);
        uint4* dd = reinterpret_cast<uint4*>(Dsm);
        for (int i = tid; i < 2408; i += 512) dd[i] = ds[i];
        const float4* x4 = reinterpret_cast<const float4*>(x);
        int xb = n*51200 + (t0*25)/4;
        for (int i = tid; i < 1600; i += 512) {
            int ci = i / 25, q = i % 25;
            float4 v = x4[xb + ci*800 + q];
            float vals[4] = {v.x, v.y, v.z, v.w};
            #pragma unroll
            for (int e = 0; e < 4; e++) {
                int pl = q*4 + e;
                int tt = (pl*41) >> 10;
                int vv = pl - tt*25;
                xsm[ci*100 + vv*4 + tt] = __float2bfloat16(vals[e]);
            }
        }
    }
    __syncthreads();
    if (tid < 400) {
        int pp = tid % 25, rq = tid / 25;
        __nv_bfloat162 acc[6][4];
        #pragma unroll
        for (int h = 0; h < 6; h++)
            #pragma unroll
            for (int j = 0; j < 4; j++) acc[h][j] = u2b(0u);
        #pragma unroll 4
        for (int ci = 0; ci < 64; ci++) {
            const uint4* wb = reinterpret_cast<const uint4*>(g_Wcp + ci*256 + rq*16);
            uint4 w0 = __ldg(wb), w1 = __ldg(wb + 1);
            __nv_bfloat162 wp[6] = {u2b(w0.x), u2b(w0.y), u2b(w0.z),
                                    u2b(w0.w), u2b(w1.x), u2b(w1.y)};
            uint2 xq = *reinterpret_cast<const uint2*>(xsm + ci*100 + pp*4);
            __nv_bfloat162 xa = u2b(xq.x), xb2 = u2b(xq.y);
            __nv_bfloat162 xs[4];
            xs[0] = __bfloat162bfloat162(__low2bfloat16(xa));
            xs[1] = __bfloat162bfloat162(__high2bfloat16(xa));
            xs[2] = __bfloat162bfloat162(__low2bfloat16(xb2));
            xs[3] = __bfloat162bfloat162(__high2bfloat16(xb2));
            #pragma unroll
            for (int h = 0; h < 6; h++)
                #pragma unroll
                for (int j = 0; j < 4; j++)
                    acc[h][j] = __hfma2(wp[h], xs[j], acc[h][j]);
        }
        int r0 = rq * 12;
        #pragma unroll
        for (int h = 0; h < 6; h++) {
            __nv_bfloat162 lo01 = __lows2bfloat162(acc[h][0], acc[h][1]);
            __nv_bfloat162 lo23 = __lows2bfloat162(acc[h][2], acc[h][3]);
            __nv_bfloat162 hi01 = __highs2bfloat162(acc[h][0], acc[h][1]);
            __nv_bfloat162 hi23 = __highs2bfloat162(acc[h][2], acc[h][3]);
            __nv_bfloat162 be = bcs[r0 + 2*h], bo = bcs[r0 + 2*h + 1];
            int re = r0 + 2*h, ro = re + 1;
            m2u[re*51 + pp*2]     = b2u(__hadd2(lo01, be));
            m2u[re*51 + pp*2 + 1] = b2u(__hadd2(lo23, be));
            m2u[ro*51 + pp*2]     = b2u(__hadd2(hi01, bo));
            m2u[ro*51 + pp*2 + 1] = b2u(__hadd2(hi23, bo));
        }
    }
    __syncthreads();
    {
        int c = tid & 63, wq = (tid >> 6) & 3, th = tid >> 8;
        int g = c & 7;
        __nv_bfloat162 acc[2][4];
        #pragma unroll
        for (int tt = 0; tt < 2; tt++)
            #pragma unroll
            for (int j = 0; j < 4; j++) acc[tt][j] = u2b(0u);
        const uint4* Dv = reinterpret_cast<const uint4*>(Dsm);
        #pragma unroll
        for (int k = 0; k < 3; k++) {
            const unsigned* mrow = m2u + (k*64 + c)*51 + th;
            const uint4* db = Dv + g*301 + k*100 + wq;
            #pragma unroll 5
            for (int v = 0; v < 25; v++) {
                uint4 dq = db[v*4];
                __nv_bfloat162 d0 = u2b(dq.x), d1 = u2b(dq.y),
                               d2 = u2b(dq.z), d3 = u2b(dq.w);
                __nv_bfloat162 mp = u2b(mrow[v*2]);
                __nv_bfloat162 m0 = __bfloat162bfloat162(__low2bfloat16(mp));
                __nv_bfloat162 m1 = __bfloat162bfloat162(__high2bfloat16(mp));
                acc[0][0] = __hfma2(m0, d0, acc[0][0]);
                acc[0][1] = __hfma2(m0, d1, acc[0][1]);
                acc[0][2] = __hfma2(m0, d2, acc[0][2]);
                acc[0][3] = __hfma2(m0, d3, acc[0][3]);
                acc[1][0] = __hfma2(m1, d0, acc[1][0]);
                acc[1][1] = __hfma2(m1, d1, acc[1][1]);
                acc[1][2] = __hfma2(m1, d2, acc[1][2]);
                acc[1][3] = __hfma2(m1, d3, acc[1][3]);
            }
        }
        float csum = 0.f;
        #pragma unroll
        for (int j = 0; j < 4; j++) {
            int w0 = wq*8 + 2*j;
            if (w0 > 24) continue;
            float s0 = 0.f, s1 = 0.f;
            #pragma unroll
            for (int tt = 0; tt < 2; tt++) {
                int trow = th*2 + tt;
                *reinterpret_cast<__nv_bfloat162*>(ybuf + (c*4 + trow)*26 + w0) = acc[tt][j];
                float2 f = __bfloat1622float2(acc[tt][j]);
                s0 += f.x; s1 += f.y;
            }
            csum += s0;
            if (w0 + 1 < 25) csum += s1;
            #pragma unroll
            for (int off = 16; off > 0; off >>= 1) {
                s0 += __shfl_xor_sync(0xffffffffu, s0, off);
                s1 += __shfl_xor_sync(0xffffffffu, s1, off);
            }
            if ((tid & 31) == 0) {
                atomicAdd(&red[w0], s0);
                if (w0 + 1 < 25) atomicAdd(&red[w0 + 1], s1);
            }
        }
        atomicAdd(&red[32 + c], csum);
    }
    __syncthreads();
    for (int i = tid; i < 1600; i += 512) {
        int c = i / 25, q = i % 25;
        uint2 u;
        __nv_bfloat16* tmp = reinterpret_cast<__nv_bfloat16*>(&u);
        #pragma unroll
        for (int e = 0; e < 4; e++) {
            int lin = q*4 + e;
            int tt = (lin*41) >> 10;
            int w = lin - tt*25;
            tmp[e] = ybuf[(c*4 + tt)*26 + w];
        }
        *reinterpret_cast<uint2*>(g_y1 + n*204800 + c*3200 + t0*25 + q*4) = u;
    }
    if (tid < 25) atomicAdd(&g_y1sum_nv[n*25 + tid], red[tid]);
    if (tid >= 32 && tid < 96) atomicAdd(&g_y1sum_nc[n*64 + tid - 32], red[tid]);
}

// ---------------- K76: fused A12l/gate + Y pass + BN stats (R14 + parallel ytsum) ----------------
__global__ void k76(const float* ws1p, const float* ws2p,
                    const float* __restrict__ We, const float* __restrict__ be,
                    const float* __restrict__ kca) {
    __shared__ float A12ls[150], Wes[512], bes[64], gates[64], ytile[768], zs[3200];
    __shared__ float a1ls[6], ytsum[48], Asum[6], Ssum[8], qs[64];
    int n = blockIdx.x, t0 = blockIdx.y * 16, tid = threadIdx.x;
    for (int i = tid; i < 512; i += 256) Wes[i] = We[i];
    if (tid < 64) bes[tid] = be[tid];
    for (int i = tid; i < 768; i += 256) {
        int o = i / 96, r = i % 96, t = r / 6, j = r % 6;
        ytile[i] = g_ysm[(n*8 + o)*768 + (t0 + t)*6 + j];
    }
    if (tid < 6) a1ls[tid] = fmaxf((*ws1p) * g_ybarS[n*6 + tid], 0.f);
    // ytsum: 48 entries x 4 partials of 32 t's (threads 0..191)
    {
        int entry = tid >> 2, part = tid & 3;
        if (entry < 48) {
            int o = entry / 6, j = entry % 6;
            const float* yp = g_ysm + (n*8 + o)*768 + part*192 + j;
            float s = 0.f;
            #pragma unroll
            for (int t = 0; t < 32; t++) s += yp[t*6];
            s += __shfl_down_sync(0xffffffffu, s, 2);
            s += __shfl_down_sync(0xffffffffu, s, 1);
            if (part == 0) ytsum[entry] = s;
        }
    }
    __syncthreads();
    if (tid < 25) {
        float a2 = fmaxf((*ws2p) * g_y1sum_nv[n*25 + tid] * (1.f/8192.f), 0.f);
        float e[6], mx = -1e30f;
        #pragma unroll
        for (int j = 0; j < 6; j++) { e[j] = a1ls[j] * a2; mx = fmaxf(mx, e[j]); }
        float s = 0.f;
        #pragma unroll
        for (int j = 0; j < 6; j++) { e[j] = expf(e[j] - mx); s += e[j]; }
        float inv = 1.f / s;
        #pragma unroll
        for (int j = 0; j < 6; j++) A12ls[j*25 + tid] = e[j] * inv;
    }
    __syncthreads();
    if (tid < 6) {
        float s = 0.f;
        for (int v = 0; v < 25; v++) s += A12ls[tid*25 + v];
        Asum[tid] = s;
    }
    __syncthreads();
    if (tid < 8) {
        float s = 0.f;
        #pragma unroll
        for (int j = 0; j < 6; j++) s += ytsum[tid*6 + j] * Asum[j];
        Ssum[tid] = s;
    }
    __syncthreads();
    if (tid < 64) {
        float yls = 3200.f * bes[tid];
        #pragma unroll
        for (int o = 0; o < 8; o++) yls += Wes[tid*8 + o] * Ssum[o];
        qs[tid] = (g_y1sum_nc[n*64 + tid] + 0.5f * yls) * (1.f/3200.f);
    }
    __syncthreads();
    if (tid < 64) {
        float qm = (tid > 0) ? qs[tid-1] : 0.f;
        float q0 = qs[tid];
        float qp1 = (tid < 63) ? qs[tid+1] : 0.f;
        float qc = kca[0]*qm + kca[1]*q0 + kca[2]*qp1;
        gates[tid] = 1.f + 1.f/(1.f + expf(-qc));
    }
    __syncthreads();
    for (int i = tid; i < 3200; i += 256) {
        int o = i / 400, r = i % 400, t = r / 25, v = r % 25;
        float s = 0.f;
        #pragma unroll
        for (int j = 0; j < 6; j++) s += ytile[o*96 + t*6 + j] * A12ls[j*25 + v];
        zs[i] = s;
    }
    __syncthreads();
    int warp = tid >> 5, lane = tid & 31;
    for (int cc = warp; cc < 64; cc += 8) {
        float wrow[8];
        #pragma unroll
        for (int o = 0; o < 8; o++) wrow[o] = Wes[cc*8 + o];
        float bc = bes[cc], gt = gates[cc];
        float lsy = 0.f, lsyy = 0.f;
        int base = ((n*64 + cc)*128 + t0)*25;
        __nv_bfloat16* yb16 = g_y1 + base;
        for (int e = lane; e < 400; e += 32) {
            float yl = bc;
            #pragma unroll
            for (int o = 0; o < 8; o++) yl += wrow[o] * zs[o*400 + e];
            float Y = (0.5f*yl + __bfloat162float(yb16[e])) * gt;
            yb16[e] = __float2bfloat16(Y);
            lsy += Y;
            lsyy += Y * Y;
        }
        #pragma unroll
        for (int off = 16; off > 0; off >>= 1) {
            lsy  += __shfl_down_sync(0xffffffffu, lsy, off);
            lsyy += __shfl_down_sync(0xffffffffu, lsyy, off);
        }
        if (lane == 0) {
            atomicAdd(&g_SY[cc], lsy);
            atomicAdd(&g_SYY[cc], lsyy);
        }
    }
}

// ---------------- K9: out = relu(BN(Yg) + x), BN inline ----------------
__global__ void __launch_bounds__(512) k9(const float* __restrict__ x,
                   const float* __restrict__ bn_g, const float* __restrict__ bn_b,
                   float* __restrict__ out) {
    int i = blockIdx.x * 512 + threadIdx.x;
    if (i >= 3276800) return;
    int c = (i / 800) & 63;
    const float icnt = 1.f/204800.f;
    float mu = g_SY[c] * icnt;
    float var = g_SYY[c] * icnt - mu*mu;
    float sc = bn_g[c] * rsqrtf(var + 1e-5f);
    float sh = bn_b[c] - mu*sc;
    const __nv_bfloat162* y2 = reinterpret_cast<const __nv_bfloat162*>(g_y1);
    __nv_bfloat162 ya = y2[i*2], yb = y2[i*2 + 1];
    float4 xv = reinterpret_cast<const float4*>(x)[i];
    float4 o;
    o.x = fmaxf(__bfloat162float(ya.x)*sc + sh + xv.x, 0.f);
    o.y = fmaxf(__bfloat162float(ya.y)*sc + sh + xv.y, 0.f);
    o.z = fmaxf(__bfloat162float(yb.x)*sc + sh + xv.z, 0.f);
    o.w = fmaxf(__bfloat162float(yb.y)*sc + sh + xv.w, 0.f);
    reinterpret_cast<float4*>(out)[i] = o;
}

// ---------------- launch ----------------
extern "C" void kernel_launch(void* const* d_in, const int* in_sizes, int n_in,
                              void* d_out, int out_size) {
    const float* x     = (const float*)d_in[0];
    const float* Dpap  = (const float*)d_in[1];
    const float* pa    = (const float*)d_in[2];
    const float* DecA  = (const float*)d_in[3];
    const float* A1buf = (const float*)d_in[4];
    const float* Wp    = (const float*)d_in[5];
    const float* bp    = (const float*)d_in[6];
    const float* Ws    = (const float*)d_in[7];
    const float* bs    = (const float*)d_in[8];
    const float* W1    = (const float*)d_in[9];
    const float* b1    = (const float*)d_in[10];
    const float* W2    = (const float*)d_in[11];
    const float* b2    = (const float*)d_in[12];
    const float* We    = (const float*)d_in[13];
    const float* be    = (const float*)d_in[14];
    const float* wt1   = (const float*)d_in[15];
    const float* wt2   = (const float*)d_in[16];
    const float* wtw1  = (const float*)d_in[17];
    const float* wtw2  = (const float*)d_in[18];
    const float* wtw11 = (const float*)d_in[19];
    const float* wtw21 = (const float*)d_in[20];
    const float* ws1   = (const float*)d_in[21];
    const float* ws2   = (const float*)d_in[22];
    const float* kca   = (const float*)d_in[23];
    const float* bn_g  = (const float*)d_in[24];
    const float* bn_b  = (const float*)d_in[25];
    float* out = (float*)d_out;

    cudaFuncSetAttribute(k5, cudaFuncAttributeMaxDynamicSharedMemorySize,
                         K5_SMEM_BYTES);
    cudaFuncSetAttribute(k1f, cudaFuncAttributeMaxDynamicSharedMemorySize,
                         K1_SMEM_BYTES);

    k1f<<<520, 512, K1_SMEM_BYTES>>>(x, Wp, bp, W2, Ws, b2, bs,
                                     Dpap, pa, DecA, A1buf);
    k2<<<64, 512>>>(wt1, wt2, wtw1, wtw2, wtw11, wtw21, W1, b1);
    k5<<<dim3(64, 32), 512, K5_SMEM_BYTES>>>(x);
    k76<<<dim3(64, 8), 256>>>(ws1, ws2, We, be, kca);
    k9<<<6400, 512>>>(x, bn_g, bn_b, out);
}

// round 17
// speedup vs baseline: 1.5949x; 1.0204x over previous
#include <cuda_runtime.h>
#include <cuda_bf16.h>
#include <math.h>

#define NN 64
#define CC 64
#define TT_ 128
#define VV 25

// ---------------- device scratch ----------------
__device__ float g_x1[NN*8*TT_*VV];
__device__ float g_xbarp[NN*8*1600];
__device__ __nv_bfloat162 g_D2[NN*9632];
__device__ float g_ysm[NN*8*TT_*6];
__device__ float g_ybarS[NN*6];
__device__ __nv_bfloat16 g_y1[NN*CC*TT_*VV];
__device__ float g_y1sum_nv[NN*VV];
__device__ float g_y1sum_nc[NN*CC];
__device__ float g_SY[CC], g_SYY[CC];
__device__ __nv_bfloat16 g_Wcp[64*256];
__device__ __nv_bfloat162 g_bc2[192];
__device__ float g_WpMean[64], g_WsMean[64];
__device__ float g_bpMean[1], g_bsMean[1];
__device__ float g_nlp[864];
__device__ float g_nlA[15000];

__device__ const int c_joints[6] = {3, 20, 7, 11, 14, 18};

__device__ __forceinline__ __nv_bfloat162 u2b(unsigned u) {
    union { unsigned u; __nv_bfloat162 b; } cv; cv.u = u; return cv.b;
}
__device__ __forceinline__ unsigned b2u(__nv_bfloat162 b) {
    union { __nv_bfloat162 b; unsigned u; } cv; cv.b = b; return cv.u;
}

// ---------------- K1f: x1 conv + xbar partials + weight folding ----------------
#define K1_SMEM_BYTES (51200 + 2048 + 32)
__global__ void __launch_bounds__(512) k1f(const float* __restrict__ x,
                                           const float* __restrict__ Wp,
                                           const float* __restrict__ bp,
                                           const float* __restrict__ W2,
                                           const float* __restrict__ Ws,
                                           const float* __restrict__ b2,
                                           const float* __restrict__ bs,
                                           const float* __restrict__ Dpap,
                                           const float* __restrict__ pa,
                                           const float* __restrict__ DecA,
                                           const float* __restrict__ A1buf) {
    int bx = blockIdx.x, tid = threadIdx.x;
    if (bx >= 512) {
        int b = bx - 512;
        if (b < 4) {
            for (int q = tid; q < 3072; q += 512) {
                int idx = b*3072 + q;
                int cj = idx / 192, r = idx % 192;
                float s = 0.f;
                #pragma unroll 8
                for (int cm = 0; cm < 64; cm++) s += W2[r*64 + cm] * Ws[cm*64 + cj];
                g_Wcp[cj*256 + (r/12)*16 + (r%12)] = __float2bfloat16(s);
            }
        } else if (b == 4) {
            for (int r = tid; r < 192; r += 512) {
                float s = 0.f;
                for (int cm = 0; cm < 64; cm++) s += W2[r*64 + cm] * bs[cm];
                g_bc2[r] = __bfloat162bfloat162(__float2bfloat16(s + b2[r]));
            }
            for (int ci = tid; ci < 64; ci += 512) {
                float s = 0.f;
                for (int o = 0; o < 8; o++) s += Wp[o*64 + ci];
                g_WpMean[ci] = s * (1.f/8.f);
                float s2 = 0.f;
                for (int c = 0; c < 64; c++) s2 += Ws[c*64 + ci];
                g_WsMean[ci] = s2 * (1.f/64.f);
            }
            if (tid == 0) {
                float s = 0.f; for (int o = 0; o < 8; o++) s += bp[o];
                g_bpMean[0] = s * (1.f/8.f);
                float s2 = 0.f; for (int c = 0; c < 64; c++) s2 += bs[c];
                g_bsMean[0] = s2 * (1.f/64.f);
            }
        } else if (b == 5) {
            for (int i = tid; i < 864; i += 512) g_nlp[i] = Dpap[i] + pa[i];
            for (int i = tid; i < NN*CC; i += 512) g_y1sum_nc[i] = 0.f;
            for (int i = tid; i < NN*VV; i += 512) g_y1sum_nv[i] = 0.f;
            if (tid < CC) { g_SY[tid] = 0.f; g_SYY[tid] = 0.f; }
        } else {
            int lo = (b - 6) * 7500;
            for (int i = tid; i < 7500; i += 512) g_nlA[lo + i] = A1buf[lo + i] + DecA[lo + i];
        }
        return;
    }
    extern __shared__ char sm1[];
    __nv_bfloat16* xt = reinterpret_cast<__nv_bfloat16*>(sm1);
    float* Wps = reinterpret_cast<float*>(sm1 + 51200);
    float* bps = Wps + 512;
    int n = bx >> 3, yb = bx & 7, t0 = yb * 16;
    const float4* x4 = reinterpret_cast<const float4*>(x);
    __nv_bfloat162* xt2 = reinterpret_cast<__nv_bfloat162*>(xt);
    int xbase4 = n*51200 + yb*100;
    for (int i = tid; i < 6400; i += 512) {
        int ci = i / 100, q = i % 100;
        float4 v = x4[xbase4 + ci*800 + q];
        xt2[ci*200 + q*2]     = __floats2bfloat162_rn(v.x, v.y);
        xt2[ci*200 + q*2 + 1] = __floats2bfloat162_rn(v.z, v.w);
    }
    if (tid < 512) Wps[tid] = Wp[tid];
    if (tid < 8) bps[tid] = bp[tid];
    __syncthreads();
    if (tid < 400) {
        int p = tid;
        float acc[8];
        #pragma unroll
        for (int o = 0; o < 8; o++) acc[o] = bps[o];
        #pragma unroll 8
        for (int ci = 0; ci < 64; ci++) {
            float xv = __bfloat162float(xt[ci*400 + p]);
            #pragma unroll
            for (int o = 0; o < 8; o++) acc[o] += Wps[o*64 + ci] * xv;
        }
        int base = (n*8*128 + t0)*25 + p;
        #pragma unroll
        for (int o = 0; o < 8; o++) g_x1[base + o*3200] = acc[o];
    } else {
        for (int i = tid - 400; i < 1600; i += 112) {
            int ci = i / 25, v = i % 25;
            float s = 0.f;
            #pragma unroll
            for (int tt = 0; tt < 16; tt++)
                s += __bfloat162float(xt[ci*400 + tt*25 + v]);
            g_xbarp[(n*8 + yb)*1600 + i] = s;
        }
    }
}

// ---------------- K2: stats + softmaxes + GCN + small-branch y + D2 pack ----------------
__global__ void __launch_bounds__(512) k2(const float* wt1p, const float* wt2p,
                   const float* wtw1p, const float* wtw2p,
                   const float* wtw11p, const float* wtw21p,
                   const float* __restrict__ W1, const float* __restrict__ b1) {
    __shared__ float xbs[1600];
    __shared__ float mb[25], xm2s[25], a1s[6], a2s[25], A12s[150], xms[6], atts[36];
    __shared__ float at2s[625];
    __shared__ float gcns[6144];
    __shared__ float W1s[192], b1s[24], Efb[864], yred[6];
    int n = blockIdx.x, tid = threadIdx.x;
    for (int i = tid; i < 1600; i += 512) {
        float s = 0.f;
        #pragma unroll
        for (int yb = 0; yb < 8; yb++) s += g_xbarp[(n*8 + yb)*1600 + i];
        xbs[i] = s;
    }
    if (tid < 192) W1s[tid] = W1[tid];
    if (tid < 24) b1s[tid] = b1[tid];
    if (tid < 6) yred[tid] = 0.f;
    __syncthreads();
    if (tid < 25) {
        float d1 = 0.f, d2 = 0.f;
        for (int ci = 0; ci < 64; ci++) {
            float xv = xbs[ci*25 + tid] * (1.f/128.f);
            d1 += xv * g_WpMean[ci];
            d2 += xv * g_WsMean[ci];
        }
        mb[tid] = d1 + g_bpMean[0];
        xm2s[tid] = d2 + g_bsMean[0];
    }
    __syncthreads();
    float wt1 = *wt1p, wt2 = *wt2p;
    if (tid < 25) a2s[tid] = fmaxf(wt2 * mb[tid], 0.f);
    if (tid < 6)  a1s[tid] = fmaxf(wt1 * mb[c_joints[tid]], 0.f);
    __syncthreads();
    if (tid < 25) {
        float e[6], mx = -1e30f;
        #pragma unroll
        for (int j = 0; j < 6; j++) { e[j] = a1s[j] * a2s[tid]; mx = fmaxf(mx, e[j]); }
        float sm = 0.f;
        #pragma unroll
        for (int j = 0; j < 6; j++) { e[j] = expf(e[j] - mx); sm += e[j]; }
        float inv = 1.f / sm;
        #pragma unroll
        for (int j = 0; j < 6; j++) A12s[j*25 + tid] = e[j] * inv;
    }
    __syncthreads();
    if (tid < 6) {
        float s = 0.f;
        for (int v = 0; v < 25; v++) s += mb[v] * A12s[tid*25 + v];
        xms[tid] = s;
    }
    __syncthreads();
    float wtw1 = *wtw1p, wtw2 = *wtw2p;
    if (tid < 6) {
        float r2w = fmaxf(wtw2 * xms[tid], 0.f);
        float e[6], mx = -1e30f;
        #pragma unroll
        for (int j = 0; j < 6; j++) { e[j] = fmaxf(wtw1 * xms[j], 0.f) * r2w; mx = fmaxf(mx, e[j]); }
        float sm = 0.f;
        #pragma unroll
        for (int j = 0; j < 6; j++) { e[j] = expf(e[j] - mx); sm += e[j]; }
        float inv = 1.f / sm;
        #pragma unroll
        for (int j = 0; j < 6; j++) atts[j*6 + tid] = e[j] * inv;
    }
    float wtw11 = *wtw11p, wtw21 = *wtw21p;
    if (tid < 25) {
        float r2w = fmaxf(wtw21 * xm2s[tid], 0.f);
        float e[25], mx = -1e30f;
        #pragma unroll
        for (int v = 0; v < 25; v++) { e[v] = fmaxf(wtw11 * xm2s[v], 0.f) * r2w; mx = fmaxf(mx, e[v]); }
        float sm = 0.f;
        #pragma unroll
        for (int v = 0; v < 25; v++) { e[v] = expf(e[v] - mx); sm += e[v]; }
        float inv = 1.f / sm;
        #pragma unroll
        for (int v = 0; v < 25; v++) at2s[v*25 + tid] = e[v] * inv;
    }
    __syncthreads();
    for (int ot = tid; ot < 1024; ot += 512) {
        int o = ot >> 7, t = ot & 127;
        const float* xr = g_x1 + ((n*8 + o)*128 + t)*25;
        float xv[25];
        #pragma unroll
        for (int v = 0; v < 25; v++) xv[v] = xr[v];
        #pragma unroll
        for (int j = 0; j < 6; j++) {
            float s = 0.f;
            #pragma unroll
            for (int v = 0; v < 25; v++) s += xv[v] * A12s[j*25 + v];
            gcns[(o*128 + t)*6 + j] = s;
        }
    }
    for (int i = tid; i < 864; i += 512) Efb[i] = 0.5f * atts[i % 36] + g_nlp[i];
    __syncthreads();
    {
        float lsum[6] = {0.f, 0.f, 0.f, 0.f, 0.f, 0.f};
        for (int gt = tid; gt < 1024; gt += 512) {
            int g = gt >> 7, t = gt & 127;
            float mloc[3][6];
            #pragma unroll
            for (int k = 0; k < 3; k++) {
                const float* wrow = &W1s[(k*8 + g)*8];
                float bb = b1s[k*8 + g];
                #pragma unroll
                for (int j = 0; j < 6; j++) {
                    float s = bb;
                    #pragma unroll
                    for (int o = 0; o < 8; o++) s += gcns[(o*128 + t)*6 + j] * wrow[o];
                    mloc[k][j] = s;
                }
            }
            #pragma unroll
            for (int w = 0; w < 6; w++) {
                float s = 0.f;
                #pragma unroll
                for (int k = 0; k < 3; k++)
                    #pragma unroll
                    for (int j = 0; j < 6; j++)
                        s += mloc[k][j] * Efb[((k*8 + g)*6 + j)*6 + w];
                g_ysm[(n*8 + g)*768 + t*6 + w] = s;
                lsum[w] += s;
            }
        }
        #pragma unroll
        for (int w = 0; w < 6; w++) {
            float s = lsum[w];
            #pragma unroll
            for (int off = 16; off > 0; off >>= 1)
                s += __shfl_xor_sync(0xffffffffu, s, off);
            if ((tid & 31) == 0) atomicAdd(&yred[w], s);
        }
    }
    for (int i = tid; i < 9632; i += 512) {
        int g = i / 1204, r = i % 1204;
        int kv = r >> 4, w2 = r & 15;
        float v0 = 0.f, v1 = 0.f;
        if (kv < 75) {
            int k = kv / 25, v = kv % 25;
            int w0 = w2*2, w1 = w0 + 1;
            if (w0 < 25) v0 = g_nlA[((k*8 + g)*25 + v)*25 + w0] + 0.5f * at2s[v*25 + w0];
            if (w1 < 25) v1 = g_nlA[((k*8 + g)*25 + v)*25 + w1] + 0.5f * at2s[v*25 + w1];
        }
        g_D2[n*9632 + i] = __floats2bfloat162_rn(v0, v1);
    }
    __syncthreads();
    if (tid < 6) g_ybarS[n*6 + tid] = yred[tid] * (1.f/1024.f);
}

// ---------------- K5: y1 kernel (R11 winner, unchanged) ----------------
#define K5_D_OFF 0
#define K5_M_OFF 38528
#define K5_X_OFF 77696
#define K5_R_OFF 91008
#define K5_B_OFF 91520
#define K5_SMEM_BYTES 92288
__global__ void __launch_bounds__(512, 2) k5(const float* __restrict__ x) {
    extern __shared__ char smem[];
    __nv_bfloat162* Dsm = reinterpret_cast<__nv_bfloat162*>(smem + K5_D_OFF);
    unsigned* m2u = reinterpret_cast<unsigned*>(smem + K5_M_OFF);
    __nv_bfloat16*  xsm = reinterpret_cast<__nv_bfloat16*>(smem + K5_X_OFF);
    __nv_bfloat16*  ybuf = reinterpret_cast<__nv_bfloat16*>(smem + K5_X_OFF);
    float* red = reinterpret_cast<float*>(smem + K5_R_OFF);
    __nv_bfloat162* bcs = reinterpret_cast<__nv_bfloat162*>(smem + K5_B_OFF);
    int n = blockIdx.x, t0 = blockIdx.y * 4, tid = threadIdx.x;
    if (tid < 128) red[tid] = 0.f;
    if (tid < 192) bcs[tid] = g_bc2[tid];
    {
        const uint4* ds = reinterpret_cast<const uint4*>(g_D2 + n*9632);
        uint4* dd = reinterpret_cast<uint4*>(Dsm);
        for (int i = tid; i < 2408; i += 512) dd[i] = ds[i];
        const float4* x4 = reinterpret_cast<const float4*>(x);
        int xb = n*51200 + (t0*25)/4;
        for (int i = tid; i < 1600; i += 512) {
            int ci = i / 25, q = i % 25;
            float4 v = x4[xb + ci*800 + q];
            float vals[4] = {v.x, v.y, v.z, v.w};
            #pragma unroll
            for (int e = 0; e < 4; e++) {
                int pl = q*4 + e;
                int tt = (pl*41) >> 10;
                int vv = pl - tt*25;
                xsm[ci*100 + vv*4 + tt] = __float2bfloat16(vals[e]);
            }
        }
    }
    __syncthreads();
    if (tid < 400) {
        int pp = tid % 25, rq = tid / 25;
        __nv_bfloat162 acc[6][4];
        #pragma unroll
        for (int h = 0; h < 6; h++)
            #pragma unroll
            for (int j = 0; j < 4; j++) acc[h][j] = u2b(0u);
        #pragma unroll 4
        for (int ci = 0; ci < 64; ci++) {
            const uint4* wb = reinterpret_cast<const uint4*>(g_Wcp + ci*256 + rq*16);
            uint4 w0 = __ldg(wb), w1 = __ldg(wb + 1);
            __nv_bfloat162 wp[6] = {u2b(w0.x), u2b(w0.y), u2b(w0.z),
                                    u2b(w0.w), u2b(w1.x), u2b(w1.y)};
            uint2 xq = *reinterpret_cast<const uint2*>(xsm + ci*100 + pp*4);
            __nv_bfloat162 xa = u2b(xq.x), xb2 = u2b(xq.y);
            __nv_bfloat162 xs[4];
            xs[0] = __bfloat162bfloat162(__low2bfloat16(xa));
            xs[1] = __bfloat162bfloat162(__high2bfloat16(xa));
            xs[2] = __bfloat162bfloat162(__low2bfloat16(xb2));
            xs[3] = __bfloat162bfloat162(__high2bfloat16(xb2));
            #pragma unroll
            for (int h = 0; h < 6; h++)
                #pragma unroll
                for (int j = 0; j < 4; j++)
                    acc[h][j] = __hfma2(wp[h], xs[j], acc[h][j]);
        }
        int r0 = rq * 12;
        #pragma unroll
        for (int h = 0; h < 6; h++) {
            __nv_bfloat162 lo01 = __lows2bfloat162(acc[h][0], acc[h][1]);
            __nv_bfloat162 lo23 = __lows2bfloat162(acc[h][2], acc[h][3]);
            __nv_bfloat162 hi01 = __highs2bfloat162(acc[h][0], acc[h][1]);
            __nv_bfloat162 hi23 = __highs2bfloat162(acc[h][2], acc[h][3]);
            __nv_bfloat162 be = bcs[r0 + 2*h], bo = bcs[r0 + 2*h + 1];
            int re = r0 + 2*h, ro = re + 1;
            m2u[re*51 + pp*2]     = b2u(__hadd2(lo01, be));
            m2u[re*51 + pp*2 + 1] = b2u(__hadd2(lo23, be));
            m2u[ro*51 + pp*2]     = b2u(__hadd2(hi01, bo));
            m2u[ro*51 + pp*2 + 1] = b2u(__hadd2(hi23, bo));
        }
    }
    __syncthreads();
    {
        int c = tid & 63, wq = (tid >> 6) & 3, th = tid >> 8;
        int g = c & 7;
        __nv_bfloat162 acc[2][4];
        #pragma unroll
        for (int tt = 0; tt < 2; tt++)
            #pragma unroll
            for (int j = 0; j < 4; j++) acc[tt][j] = u2b(0u);
        const uint4* Dv = reinterpret_cast<const uint4*>(Dsm);
        #pragma unroll
        for (int k = 0; k < 3; k++) {
            const unsigned* mrow = m2u + (k*64 + c)*51 + th;
            const uint4* db = Dv + g*301 + k*100 + wq;
            #pragma unroll 5
            for (int v = 0; v < 25; v++) {
                uint4 dq = db[v*4];
                __nv_bfloat162 d0 = u2b(dq.x), d1 = u2b(dq.y),
                               d2 = u2b(dq.z), d3 = u2b(dq.w);
                __nv_bfloat162 mp = u2b(mrow[v*2]);
                __nv_bfloat162 m0 = __bfloat162bfloat162(__low2bfloat16(mp));
                __nv_bfloat162 m1 = __bfloat162bfloat162(__high2bfloat16(mp));
                acc[0][0] = __hfma2(m0, d0, acc[0][0]);
                acc[0][1] = __hfma2(m0, d1, acc[0][1]);
                acc[0][2] = __hfma2(m0, d2, acc[0][2]);
                acc[0][3] = __hfma2(m0, d3, acc[0][3]);
                acc[1][0] = __hfma2(m1, d0, acc[1][0]);
                acc[1][1] = __hfma2(m1, d1, acc[1][1]);
                acc[1][2] = __hfma2(m1, d2, acc[1][2]);
                acc[1][3] = __hfma2(m1, d3, acc[1][3]);
            }
        }
        float csum = 0.f;
        #pragma unroll
        for (int j = 0; j < 4; j++) {
            int w0 = wq*8 + 2*j;
            if (w0 > 24) continue;
            float s0 = 0.f, s1 = 0.f;
            #pragma unroll
            for (int tt = 0; tt < 2; tt++) {
                int trow = th*2 + tt;
                *reinterpret_cast<__nv_bfloat162*>(ybuf + (c*4 + trow)*26 + w0) = acc[tt][j];
                float2 f = __bfloat1622float2(acc[tt][j]);
                s0 += f.x; s1 += f.y;
            }
            csum += s0;
            if (w0 + 1 < 25) csum += s1;
            #pragma unroll
            for (int off = 16; off > 0; off >>= 1) {
                s0 += __shfl_xor_sync(0xffffffffu, s0, off);
                s1 += __shfl_xor_sync(0xffffffffu, s1, off);
            }
            if ((tid & 31) == 0) {
                atomicAdd(&red[w0], s0);
                if (w0 + 1 < 25) atomicAdd(&red[w0 + 1], s1);
            }
        }
        atomicAdd(&red[32 + c], csum);
    }
    __syncthreads();
    for (int i = tid; i < 1600; i += 512) {
        int c = i / 25, q = i % 25;
        uint2 u;
        __nv_bfloat16* tmp = reinterpret_cast<__nv_bfloat16*>(&u);
        #pragma unroll
        for (int e = 0; e < 4; e++) {
            int lin = q*4 + e;
            int tt = (lin*41) >> 10;
            int w = lin - tt*25;
            tmp[e] = ybuf[(c*4 + tt)*26 + w];
        }
        *reinterpret_cast<uint2*>(g_y1 + n*204800 + c*3200 + t0*25 + q*4) = u;
    }
    if (tid < 25) atomicAdd(&g_y1sum_nv[n*25 + tid], red[tid]);
    if (tid >= 32 && tid < 96) atomicAdd(&g_y1sum_nc[n*64 + tid - 32], red[tid]);
}

// ---------------- K76: fused A12l/gate + Y pass + BN stats (512 threads) ----------------
__global__ void __launch_bounds__(512) k76(const float* ws1p, const float* ws2p,
                    const float* __restrict__ We, const float* __restrict__ be,
                    const float* __restrict__ kca) {
    __shared__ float A12ls[150], Wes[512], bes[64], gates[64], ytile[768], zs[3200];
    __shared__ float a1ls[6], ytsum[48], Asum[6], Ssum[8], qs[64];
    int n = blockIdx.x, t0 = blockIdx.y * 16, tid = threadIdx.x;
    if (tid < 512) Wes[tid] = We[tid];
    if (tid < 64) bes[tid] = be[tid];
    for (int i = tid; i < 768; i += 512) {
        int o = i / 96, r = i % 96, t = r / 6, j = r % 6;
        ytile[i] = g_ysm[(n*8 + o)*768 + (t0 + t)*6 + j];
    }
    if (tid < 6) a1ls[tid] = fmaxf((*ws1p) * g_ybarS[n*6 + tid], 0.f);
    // ytsum: 48 entries x 4 partials of 32 t's (threads 0..191)
    {
        int entry = tid >> 2, part = tid & 3;
        if (entry < 48) {
            int o = entry / 6, j = entry % 6;
            const float* yp = g_ysm + (n*8 + o)*768 + part*192 + j;
            float s = 0.f;
            #pragma unroll
            for (int t = 0; t < 32; t++) s += yp[t*6];
            s += __shfl_down_sync(0xffffffffu, s, 2);
            s += __shfl_down_sync(0xffffffffu, s, 1);
            if (part == 0) ytsum[entry] = s;
        }
    }
    __syncthreads();
    if (tid < 25) {
        float a2 = fmaxf((*ws2p) * g_y1sum_nv[n*25 + tid] * (1.f/8192.f), 0.f);
        float e[6], mx = -1e30f;
        #pragma unroll
        for (int j = 0; j < 6; j++) { e[j] = a1ls[j] * a2; mx = fmaxf(mx, e[j]); }
        float s = 0.f;
        #pragma unroll
        for (int j = 0; j < 6; j++) { e[j] = expf(e[j] - mx); s += e[j]; }
        float inv = 1.f / s;
        #pragma unroll
        for (int j = 0; j < 6; j++) A12ls[j*25 + tid] = e[j] * inv;
    }
    __syncthreads();
    if (tid < 6) {
        float s = 0.f;
        for (int v = 0; v < 25; v++) s += A12ls[tid*25 + v];
        Asum[tid] = s;
    }
    __syncthreads();
    if (tid < 8) {
        float s = 0.f;
        #pragma unroll
        for (int j = 0; j < 6; j++) s += ytsum[tid*6 + j] * Asum[j];
        Ssum[tid] = s;
    }
    __syncthreads();
    if (tid < 64) {
        float yls = 3200.f * bes[tid];
        #pragma unroll
        for (int o = 0; o < 8; o++) yls += Wes[tid*8 + o] * Ssum[o];
        qs[tid] = (g_y1sum_nc[n*64 + tid] + 0.5f * yls) * (1.f/3200.f);
    }
    __syncthreads();
    if (tid < 64) {
        float qm = (tid > 0) ? qs[tid-1] : 0.f;
        float q0 = qs[tid];
        float qp1 = (tid < 63) ? qs[tid+1] : 0.f;
        float qc = kca[0]*qm + kca[1]*q0 + kca[2]*qp1;
        gates[tid] = 1.f + 1.f/(1.f + expf(-qc));
    }
    __syncthreads();
    for (int i = tid; i < 3200; i += 512) {
        int o = i / 400, r = i % 400, t = r / 25, v = r % 25;
        float s = 0.f;
        #pragma unroll
        for (int j = 0; j < 6; j++) s += ytile[o*96 + t*6 + j] * A12ls[j*25 + v];
        zs[i] = s;
    }
    __syncthreads();
    int warp = tid >> 5, lane = tid & 31;
    for (int cc = warp; cc < 64; cc += 16) {
        float wrow[8];
        #pragma unroll
        for (int o = 0; o < 8; o++) wrow[o] = Wes[cc*8 + o];
        float bc = bes[cc], gt = gates[cc];
        float lsy = 0.f, lsyy = 0.f;
        int base = ((n*64 + cc)*128 + t0)*25;
        __nv_bfloat16* yb16 = g_y1 + base;
        for (int e = lane; e < 400; e += 32) {
            float yl = bc;
            #pragma unroll
            for (int o = 0; o < 8; o++) yl += wrow[o] * zs[o*400 + e];
            float Y = (0.5f*yl + __bfloat162float(yb16[e])) * gt;
            yb16[e] = __float2bfloat16(Y);
            lsy += Y;
            lsyy += Y * Y;
        }
        #pragma unroll
        for (int off = 16; off > 0; off >>= 1) {
            lsy  += __shfl_down_sync(0xffffffffu, lsy, off);
            lsyy += __shfl_down_sync(0xffffffffu, lsyy, off);
        }
        if (lane == 0) {
            atomicAdd(&g_SY[cc], lsy);
            atomicAdd(&g_SYY[cc], lsyy);
        }
    }
}

// ---------------- K9: out = relu(BN(Yg) + x), BN inline ----------------
__global__ void __launch_bounds__(512) k9(const float* __restrict__ x,
                   const float* __restrict__ bn_g, const float* __restrict__ bn_b,
                   float* __restrict__ out) {
    int i = blockIdx.x * 512 + threadIdx.x;
    if (i >= 3276800) return;
    int c = (i / 800) & 63;
    const float icnt = 1.f/204800.f;
    float mu = g_SY[c] * icnt;
    float var = g_SYY[c] * icnt - mu*mu;
    float sc = bn_g[c] * rsqrtf(var + 1e-5f);
    float sh = bn_b[c] - mu*sc;
    const __nv_bfloat162* y2 = reinterpret_cast<const __nv_bfloat162*>(g_y1);
    __nv_bfloat162 ya = y2[i*2], yb = y2[i*2 + 1];
    float4 xv = reinterpret_cast<const float4*>(x)[i];
    float4 o;
    o.x = fmaxf(__bfloat162float(ya.x)*sc + sh + xv.x, 0.f);
    o.y = fmaxf(__bfloat162float(ya.y)*sc + sh + xv.y, 0.f);
    o.z = fmaxf(__bfloat162float(yb.x)*sc + sh + xv.z, 0.f);
    o.w = fmaxf(__bfloat162float(yb.y)*sc + sh + xv.w, 0.f);
    reinterpret_cast<float4*>(out)[i] = o;
}

// ---------------- launch ----------------
extern "C" void kernel_launch(void* const* d_in, const int* in_sizes, int n_in,
                              void* d_out, int out_size) {
    const float* x     = (const float*)d_in[0];
    const float* Dpap  = (const float*)d_in[1];
    const float* pa    = (const float*)d_in[2];
    const float* DecA  = (const float*)d_in[3];
    const float* A1buf = (const float*)d_in[4];
    const float* Wp    = (const float*)d_in[5];
    const float* bp    = (const float*)d_in[6];
    const float* Ws    = (const float*)d_in[7];
    const float* bs    = (const float*)d_in[8];
    const float* W1    = (const float*)d_in[9];
    const float* b1    = (const float*)d_in[10];
    const float* W2    = (const float*)d_in[11];
    const float* b2    = (const float*)d_in[12];
    const float* We    = (const float*)d_in[13];
    const float* be    = (const float*)d_in[14];
    const float* wt1   = (const float*)d_in[15];
    const float* wt2   = (const float*)d_in[16];
    const float* wtw1  = (const float*)d_in[17];
    const float* wtw2  = (const float*)d_in[18];
    const float* wtw11 = (const float*)d_in[19];
    const float* wtw21 = (const float*)d_in[20];
    const float* ws1   = (const float*)d_in[21];
    const float* ws2   = (const float*)d_in[22];
    const float* kca   = (const float*)d_in[23];
    const float* bn_g  = (const float*)d_in[24];
    const float* bn_b  = (const float*)d_in[25];
    float* out = (float*)d_out;

    cudaFuncSetAttribute(k5, cudaFuncAttributeMaxDynamicSharedMemorySize,
                         K5_SMEM_BYTES);
    cudaFuncSetAttribute(k1f, cudaFuncAttributeMaxDynamicSharedMemorySize,
                         K1_SMEM_BYTES);

    k1f<<<520, 512, K1_SMEM_BYTES>>>(x, Wp, bp, W2, Ws, b2, bs,
                                     Dpap, pa, DecA, A1buf);
    k2<<<64, 512>>>(wt1, wt2, wtw1, wtw2, wtw11, wtw21, W1, b1);
    k5<<<dim3(64, 32), 512, K5_SMEM_BYTES>>>(x);
    k76<<<dim3(64, 8), 512>>>(ws1, ws2, We, be, kca);
    k9<<<6400, 512>>>(x, bn_g, bn_b, out);
}